// round 1
// baseline (speedup 1.0000x reference)
#include <cuda_runtime.h>
#include <cstdint>

#define DIMC 512
#define EE 336
#define E3 1008
#define NSTATE 16
#define NH 6
#define HDIM 56
#define BB 8
#define LL 4096
#define NN (BB*LL)        // 32768 tokens
#define KC 819
#define DU 64             // truncated scan kernel length
#define DK 67             // combined (scan * dconv) kernel length

// ---------------- scratch (static device memory; no allocs allowed) ----------
__device__ float g_xp[(size_t)NN*EE];          // 44 MB  (xp then xpn in-place)
__device__ float g_qkv[(size_t)NN*E3];         // 132 MB
__device__ float g_att[(size_t)NN*EE];         // 44 MB  (layout e = d*NH + h)
__device__ float g_imp[NN];
__device__ int   g_idx[BB*KC];
__device__ float g_ys[(size_t)BB*KC*EE];
__device__ float g_xproc[(size_t)BB*KC*DIMC];
__device__ float g_K[EE*DK];

// ---------------- prep: combined conv kernel K[e][d] = (conv_w * sigC A^d sigB)
__global__ void prep_kernel(const float* __restrict__ A, const float* __restrict__ Bp,
                            const float* __restrict__ Cp, const float* __restrict__ cw)
{
    __shared__ float U[DU][NSTATE];
    __shared__ float gk[DU];
    __shared__ float sC[NSTATE];
    int tid = threadIdx.x;
    int e = blockIdx.x;

    // warp 0: u_{d+1} = A u_d, u_0 = sigmoid(Bp)
    if (tid < 32) {
        int i = tid & 15;
        float u = 1.f / (1.f + expf(-Bp[i]));
        for (int d = 0; d < DU; d++) {
            if (tid < 16) U[d][i] = u;
            float nu = 0.f;
            #pragma unroll
            for (int j = 0; j < 16; j++)
                nu += A[i*16 + j] * __shfl_sync(0xFFFFFFFFu, u, j);
            u = nu;
        }
    }
    if (tid < 16) sC[tid] = 1.f / (1.f + expf(-Cp[e*16 + tid]));
    __syncthreads();

    for (int d = tid; d < DU; d += blockDim.x) {
        float s = 0.f;
        #pragma unroll
        for (int i = 0; i < 16; i++) s += sC[i] * U[d][i];
        gk[d] = s;
    }
    __syncthreads();

    for (int dd = tid; dd < DK; dd += blockDim.x) {
        float s = 0.f;
        #pragma unroll
        for (int d1 = 0; d1 < 4; d1++) {
            int d2 = dd - d1;
            if (d2 >= 0 && d2 < DU) s += cw[e*4 + (3 - d1)] * gk[d2];
        }
        g_K[e*DK + dd] = s;
    }
}

// ---------------- SGEMM: C[M,N] = op(A)[M,K] @ W[K,N] + bias  --------------
// MODE 1: A element transformed by DyT: tanh(alpha*a)*dw[k]+db[k]
template<int MODE>
__global__ void __launch_bounds__(256) sgemm_kernel(
    const float* __restrict__ A, const float* __restrict__ W,
    const float* __restrict__ bias, float* __restrict__ C,
    int M, int N, int K,
    const float* __restrict__ alpha, const float* __restrict__ dw, const float* __restrict__ db)
{
    const int BM = 128, BN = 112, BK = 16, TM = 8, TN = 7;
    __shared__ float As[BK][BM + 1];
    __shared__ float Ws[BK][BN];
    int tid = threadIdx.y * 16 + threadIdx.x;
    int m0 = blockIdx.y * BM, n0 = blockIdx.x * BN;
    float a0 = (MODE == 1) ? alpha[0] : 0.f;

    float acc[TM][TN];
    #pragma unroll
    for (int i = 0; i < TM; i++)
        #pragma unroll
        for (int j = 0; j < TN; j++) acc[i][j] = 0.f;

    for (int k0 = 0; k0 < K; k0 += BK) {
        #pragma unroll
        for (int t = 0; t < (BM*BK)/256; t++) {
            int i = tid + t*256;
            int r = i >> 4, c = i & 15;
            int gm = m0 + r;
            float v = (gm < M) ? A[(size_t)gm*K + k0 + c] : 0.f;
            if (MODE == 1) v = tanhf(a0 * v) * __ldg(&dw[k0+c]) + __ldg(&db[k0+c]);
            As[c][r] = v;
        }
        #pragma unroll
        for (int t = 0; t < (BK*BN)/256; t++) {
            int i = tid + t*256;
            int r = i / BN, c = i - r*BN;
            int gn = n0 + c;
            Ws[r][c] = (gn < N) ? W[(size_t)(k0+r)*N + gn] : 0.f;
        }
        __syncthreads();
        #pragma unroll
        for (int k = 0; k < BK; k++) {
            float a[TM], b[TN];
            #pragma unroll
            for (int i = 0; i < TM; i++) a[i] = As[k][threadIdx.y*TM + i];
            #pragma unroll
            for (int j = 0; j < TN; j++) b[j] = Ws[k][threadIdx.x*TN + j];
            #pragma unroll
            for (int i = 0; i < TM; i++)
                #pragma unroll
                for (int j = 0; j < TN; j++)
                    acc[i][j] += a[i] * b[j];
        }
        __syncthreads();
    }
    #pragma unroll
    for (int i = 0; i < TM; i++) {
        int gm = m0 + threadIdx.y*TM + i;
        if (gm >= M) continue;
        #pragma unroll
        for (int j = 0; j < TN; j++) {
            int gn = n0 + threadIdx.x*TN + j;
            if (gn < N) C[(size_t)gm*N + gn] = acc[i][j] + __ldg(&bias[gn]);
        }
    }
}

// ---------------- row L2-normalize (336 cols), in place ---------------------
__global__ void norm_kernel(float* __restrict__ xp)
{
    int lane = threadIdx.x & 31;
    int row = blockIdx.x * 8 + (threadIdx.x >> 5);
    float* p = xp + (size_t)row * EE;
    float s = 0.f;
    for (int e = lane; e < EE; e += 32) { float v = p[e]; s += v*v; }
    #pragma unroll
    for (int o = 16; o > 0; o >>= 1) s += __shfl_xor_sync(0xFFFFFFFFu, s, o);
    float inv = 1.f / fmaxf(sqrtf(s), 1e-12f);
    for (int e = lane; e < EE; e += 32) p[e] *= inv;
}

// ---------------- attention: argmax over 6 keys, copy v row, imp norm ------
__global__ void attn_kernel(const float* __restrict__ qkv,
                            float* __restrict__ att, float* __restrict__ imp)
{
    __shared__ float sq[4][E3];
    __shared__ float sc[4][36];
    __shared__ int   gb[4][NH];
    int wid = threadIdx.x >> 5, lane = threadIdx.x & 31;
    int n = blockIdx.x * 4 + wid;
    const float* row = qkv + (size_t)n * E3;
    float* s = sq[wid];
    for (int e = lane; e < E3; e += 32) s[e] = row[e];
    __syncwarp();
    for (int p = lane; p < 36; p += 32) {
        int h = p / 6, g = p - h*6;
        const float* qp = s + h*HDIM;
        const float* kp = s + EE + g*HDIM;
        float d = 0.f;
        #pragma unroll
        for (int t = 0; t < HDIM; t++) d += qp[t] * kp[t];
        sc[wid][p] = d;
    }
    __syncwarp();
    if (lane < NH) {
        float best = sc[wid][lane*6]; int bg = 0;
        #pragma unroll
        for (int g = 1; g < 6; g++) {
            float v = sc[wid][lane*6 + g];
            if (v > best) { best = v; bg = g; }   // strict > : jax tie -> lowest idx
        }
        gb[wid][lane] = bg;
    }
    __syncwarp();
    float acc = 0.f;
    for (int e = lane; e < EE; e += 32) {
        int h = e % NH, d = e / NH;               // out layout: e = d*NH + h
        float v = s[2*EE + gb[wid][h]*HDIM + d];
        att[(size_t)n*EE + e] = v;
        acc += v*v;
    }
    #pragma unroll
    for (int o = 16; o > 0; o >>= 1) acc += __shfl_xor_sync(0xFFFFFFFFu, acc, o);
    if (lane == 0) imp[n] = sqrtf(acc);
}

// ---------------- exact top-819 per batch: bitonic sort of 4096 ------------
__global__ void topk_kernel(const float* __restrict__ imp, int* __restrict__ idxout)
{
    __shared__ unsigned long long key[LL];
    int b = blockIdx.x;
    for (int i = threadIdx.x; i < LL; i += blockDim.x) {
        unsigned fb = __float_as_uint(imp[b*LL + i]);  // imp >= 0: bits monotonic
        key[i] = ((unsigned long long)(0xFFFFFFFFu - fb) << 32) | (unsigned)i;
    }
    __syncthreads();
    for (int k = 2; k <= LL; k <<= 1)
        for (int j = k >> 1; j > 0; j >>= 1) {
            for (int i = threadIdx.x; i < LL; i += blockDim.x) {
                int ixj = i ^ j;
                if (ixj > i) {
                    bool up = ((i & k) == 0);
                    unsigned long long a = key[i], c = key[ixj];
                    if ((a > c) == up) { key[i] = c; key[ixj] = a; }
                }
            }
            __syncthreads();
        }
    for (int i = threadIdx.x; i < KC; i += blockDim.x)
        idxout[b*KC + i] = (int)(key[i] & 0xFFFFFFFFu);
}

// ---------------- fused gather + 67-tap per-channel causal conv ------------
// ys[b,j,e] = sum_d K[e][d] * att[b, idx[b,j-d], e]
__global__ void __launch_bounds__(224) conv_kernel(const float* __restrict__ att,
                                                   const int* __restrict__ idx,
                                                   float* __restrict__ ys)
{
    const int ET = 56, JT = 64, WIN = JT + DK - 1;  // 130
    __shared__ float sp[ET][WIN + 1];
    __shared__ float Ks[ET][DK + 1];
    __shared__ int   sidx[WIN];
    int et = blockIdx.x, jt = blockIdx.y, b = blockIdx.z;
    int e0 = et * ET, j0 = jt * JT;
    int tid = threadIdx.x;

    for (int w = tid; w < WIN; w += 224) {
        int j = j0 - (DK - 1) + w;
        sidx[w] = (j >= 0 && j < KC) ? idx[b*KC + j] : -1;
    }
    for (int i = tid; i < ET*DK; i += 224) {
        int ee = i / DK, d = i - ee*DK;
        Ks[ee][d] = g_K[(e0 + ee)*DK + d];
    }
    __syncthreads();
    for (int i = tid; i < WIN*ET; i += 224) {
        int w = i / ET, ee = i - w*ET;
        int pos = sidx[w];
        sp[ee][w] = (pos >= 0) ? att[((size_t)b*LL + pos)*EE + e0 + ee] : 0.f;
    }
    __syncthreads();

    int ee = tid % ET, jg = tid / ET;     // jg in 0..3
    float acc[16];
    #pragma unroll
    for (int t = 0; t < 16; t++) acc[t] = 0.f;
    int wbase = (DK - 1) + jg*16;
    for (int d = 0; d < DK; d++) {
        float kv = Ks[ee][d];
        #pragma unroll
        for (int t = 0; t < 16; t++)
            acc[t] += kv * sp[ee][wbase + t - d];
    }
    #pragma unroll
    for (int t = 0; t < 16; t++) {
        int j = j0 + jg*16 + t;
        if (j < KC) ys[((size_t)b*KC + j)*EE + e0 + ee] = acc[t];
    }
}

// ---------------- residual copy + scatter ----------------------------------
__global__ void residual_kernel(const float4* __restrict__ x, float4* __restrict__ out)
{
    size_t i = (size_t)blockIdx.x * blockDim.x + threadIdx.x;
    out[i] = x[i];
}

__global__ void scatter_kernel(const float* __restrict__ x, const float* __restrict__ xproc,
                               const int* __restrict__ idx, float* __restrict__ out)
{
    int row = blockIdx.x;                  // 0..BB*KC-1
    int b = row / KC, j = row - b*KC;
    int pos = idx[b*KC + j];
    const float* xp = xproc + (size_t)row * DIMC;
    size_t base = ((size_t)b*LL + pos) * DIMC;
    for (int c = threadIdx.x; c < DIMC; c += blockDim.x)
        out[base + c] = x[base + c] + xp[c];
}

// ---------------- launch ----------------------------------------------------
extern "C" void kernel_launch(void* const* d_in, const int* in_sizes, int n_in,
                              void* d_out, int out_size)
{
    const float* x      = (const float*)d_in[0];
    const float* alpha  = (const float*)d_in[1];
    const float* dyt_w  = (const float*)d_in[2];
    const float* dyt_b  = (const float*)d_in[3];
    const float* W_in   = (const float*)d_in[4];
    const float* b_in   = (const float*)d_in[5];
    const float* W_qkv  = (const float*)d_in[6];
    const float* b_qkv  = (const float*)d_in[7];
    const float* conv_w = (const float*)d_in[8];
    const float* A      = (const float*)d_in[9];
    const float* Bp     = (const float*)d_in[10];
    const float* Cp     = (const float*)d_in[11];
    const float* W_out  = (const float*)d_in[12];
    const float* b_out  = (const float*)d_in[13];
    float* out = (float*)d_out;

    float *xp, *qkv, *att, *imp, *ys, *xproc;
    int *idx;
    cudaGetSymbolAddress((void**)&xp,    g_xp);
    cudaGetSymbolAddress((void**)&qkv,   g_qkv);
    cudaGetSymbolAddress((void**)&att,   g_att);
    cudaGetSymbolAddress((void**)&imp,   g_imp);
    cudaGetSymbolAddress((void**)&idx,   g_idx);
    cudaGetSymbolAddress((void**)&ys,    g_ys);
    cudaGetSymbolAddress((void**)&xproc, g_xproc);

    dim3 thr(16, 16);

    // 0) scan->conv kernel precompute
    prep_kernel<<<EE, 128>>>(A, Bp, Cp, conv_w);

    // 1) xp = dyt(x) @ W_in + b_in   [32768,512]x[512,336]
    sgemm_kernel<1><<<dim3(3, NN/128), thr>>>(x, W_in, b_in, xp, NN, EE, DIMC, alpha, dyt_w, dyt_b);

    // 2) row-normalize
    norm_kernel<<<NN/8, 256>>>(xp);

    // 3) qkv = xpn @ W_qkv + b_qkv  [32768,336]x[336,1008]
    sgemm_kernel<0><<<dim3(9, NN/128), thr>>>(xp, W_qkv, b_qkv, qkv, NN, E3, EE, alpha, dyt_w, dyt_b);

    // 4) sparse attention (kh=1 -> argmax gather) + importance
    attn_kernel<<<NN/4, 128>>>(qkv, att, imp);

    // 5) exact sorted top-819 per batch
    topk_kernel<<<BB, 1024>>>(imp, idx);

    // 6) gather + combined dconv*scan causal convolution
    conv_kernel<<<dim3(EE/56, (KC + 63)/64, BB), 224>>>(att, idx, ys);

    // 7) xproc = ys @ W_out + b_out  [6552,336]x[336,512]
    sgemm_kernel<0><<<dim3((DIMC + 111)/112, (BB*KC + 127)/128), thr>>>(ys, W_out, b_out, xproc,
                                                                        BB*KC, DIMC, EE, alpha, dyt_w, dyt_b);

    // 8) out = residual
    residual_kernel<<<(NN*DIMC/4)/1024, 1024>>>((const float4*)x, (float4*)out);

    // 9) scatter selected rows: out[b, idx] = x + xproc
    scatter_kernel<<<BB*KC, 128>>>(x, xproc, idx, out);
}

// round 4
// speedup vs baseline: 1.3654x; 1.3654x over previous
#include <cuda_runtime.h>
#include <cstdint>

#define DIMC 512
#define EE 336
#define E3 1008
#define NSTATE 16
#define NH 6
#define HDIM 56
#define BB 8
#define LL 4096
#define NN (BB*LL)        // 32768 tokens
#define KC 819
#define DU 64             // truncated scan kernel length
#define DK 67             // combined (scan * dconv) kernel length

// ---------------- scratch (static device memory; no allocs allowed) ----------
__device__ float g_xp[(size_t)NN*EE];
__device__ float g_qkv[(size_t)NN*E3];
__device__ float g_att[(size_t)NN*EE];
__device__ float g_imp[NN];
__device__ int   g_idx[BB*KC];
__device__ float g_ys[(size_t)BB*KC*EE];
__device__ float g_xproc[(size_t)BB*KC*DIMC];
__device__ float g_K[EE*DK];

// ============================ helpers =======================================
__device__ __forceinline__ void tf32_split(float v, uint32_t& h, uint32_t& l) {
    uint32_t hb; asm("cvt.rna.tf32.f32 %0, %1;" : "=r"(hb) : "f"(v));
    float hf = __uint_as_float(hb);
    uint32_t lb; asm("cvt.rna.tf32.f32 %0, %1;" : "=r"(lb) : "f"(v - hf));
    h = hb; l = lb;
}
__device__ __forceinline__ void mma8(float* c, const uint32_t* a, const uint32_t* b) {
    asm volatile("mma.sync.aligned.m16n8k8.row.col.f32.tf32.tf32.f32 "
        "{%0,%1,%2,%3}, {%4,%5,%6,%7}, {%8,%9}, {%0,%1,%2,%3};"
        : "+f"(c[0]), "+f"(c[1]), "+f"(c[2]), "+f"(c[3])
        : "r"(a[0]), "r"(a[1]), "r"(a[2]), "r"(a[3]), "r"(b[0]), "r"(b[1]));
}

// ================== split-tf32 (3-pass) warp-MMA GEMM =======================
// C[M,N] = op(A)[M,K] @ W[K,N] + bias.  MODE 1: DyT(tanh) on A elements.
// CTA tile 128 x BN, K-chunk 32. 8 warps (4 M x 2 N), warp tile 32 x BN/2.
template<int BN, int MODE>
__global__ void __launch_bounds__(256, 1) mma_gemm(
    const float* __restrict__ A, const float* __restrict__ W,
    const float* __restrict__ bias, float* __restrict__ C,
    int M, int N, int K,
    const float* __restrict__ alpha, const float* __restrict__ dw,
    const float* __restrict__ db)
{
    constexpr int PA = 36;            // A row pitch (floats): conflict-free
    constexpr int PB = BN + 8;        // B row pitch: conflict-free frag LDS
    constexpr int WN = BN / 2;
    constexpr int NT8 = WN / 8;       // n8 tiles per warp (7 or 8)
    constexpr int BI = (BN * 32) / 256;

    extern __shared__ float sm[];
    float* As = sm;                   // [2][128][PA]
    float* Bs = sm + 2 * 128 * PA;    // [2][32][PB]

    int tid = threadIdx.x, wid = tid >> 5, lane = tid & 31;
    int wm = (wid & 3) * 32, wn = (wid >> 2) * WN;
    int g4 = lane >> 2, t4 = lane & 3;
    int m0 = blockIdx.y * 128, n0 = blockIdx.x * BN;
    float a0s = (MODE == 1) ? __ldg(alpha) : 0.f;

    float acc[2][NT8][4];
    #pragma unroll
    for (int i = 0; i < 2; i++)
        #pragma unroll
        for (int j = 0; j < NT8; j++)
            #pragma unroll
            for (int t = 0; t < 4; t++) acc[i][j][t] = 0.f;

    int NC = (K + 31) / 32;

    float4 ra[4];
    float  rb[BI];

    // ---- global -> regs for chunk c
    auto ldg_chunk = [&](int c) {
        int k0 = c * 32;
        #pragma unroll
        for (int it = 0; it < 4; it++) {
            int idx = tid + it * 256;
            int r = idx >> 3, f4 = idx & 7;
            int gm = m0 + r, gk = k0 + f4 * 4;
            float4 v = make_float4(0.f, 0.f, 0.f, 0.f);
            if (gm < M && gk < K) {
                v = *(const float4*)(A + (size_t)gm * K + gk);
                if (MODE == 1) {
                    float4 w4 = *(const float4*)(dw + gk);
                    float4 b4 = *(const float4*)(db + gk);
                    v.x = tanhf(a0s * v.x) * w4.x + b4.x;
                    v.y = tanhf(a0s * v.y) * w4.y + b4.y;
                    v.z = tanhf(a0s * v.z) * w4.z + b4.z;
                    v.w = tanhf(a0s * v.w) * w4.w + b4.w;
                }
            }
            ra[it] = v;
        }
        #pragma unroll
        for (int it = 0; it < BI; it++) {
            int idx = tid + it * 256;
            int kl = idx / BN, nr = idx - kl * BN;
            int gk = k0 + kl;
            rb[it] = (gk < K) ? __ldg(W + (size_t)gk * N + n0 + nr) : 0.f;
        }
    };
    // ---- regs -> smem buffer
    auto sts_chunk = [&](int buf) {
        float* Ab = As + buf * 128 * PA;
        float* Bb = Bs + buf * 32 * PB;
        #pragma unroll
        for (int it = 0; it < 4; it++) {
            int idx = tid + it * 256;
            int r = idx >> 3, f4 = idx & 7;
            *(float4*)(Ab + r * PA + f4 * 4) = ra[it];
        }
        #pragma unroll
        for (int it = 0; it < BI; it++) {
            int idx = tid + it * 256;
            int kl = idx / BN, nr = idx - kl * BN;
            Bb[kl * PB + nr] = rb[it];
        }
    };
    // ---- compute one 32-wide K chunk from smem buffer
    auto compute = [&](int buf) {
        const float* Ab = As + buf * 128 * PA;
        const float* Bb = Bs + buf * 32 * PB;
        #pragma unroll
        for (int kk = 0; kk < 4; kk++) {
            int k8 = kk * 8;
            uint32_t ah[2][4], al[2][4];
            #pragma unroll
            for (int mt = 0; mt < 2; mt++) {
                int r = wm + mt * 16 + g4;
                tf32_split(Ab[(r    ) * PA + k8 + t4    ], ah[mt][0], al[mt][0]);
                tf32_split(Ab[(r + 8) * PA + k8 + t4    ], ah[mt][1], al[mt][1]);
                tf32_split(Ab[(r    ) * PA + k8 + t4 + 4], ah[mt][2], al[mt][2]);
                tf32_split(Ab[(r + 8) * PA + k8 + t4 + 4], ah[mt][3], al[mt][3]);
            }
            uint32_t bh[NT8][2], bl[NT8][2];
            #pragma unroll
            for (int nt = 0; nt < NT8; nt++) {
                int n = wn + nt * 8 + g4;
                tf32_split(Bb[(k8 + t4    ) * PB + n], bh[nt][0], bl[nt][0]);
                tf32_split(Bb[(k8 + t4 + 4) * PB + n], bh[nt][1], bl[nt][1]);
            }
            #pragma unroll
            for (int mt = 0; mt < 2; mt++)
                #pragma unroll
                for (int nt = 0; nt < NT8; nt++) {
                    mma8(acc[mt][nt], ah[mt], bh[nt]);
                    mma8(acc[mt][nt], ah[mt], bl[nt]);
                    mma8(acc[mt][nt], al[mt], bh[nt]);
                }
        }
    };

    ldg_chunk(0);
    sts_chunk(0);
    __syncthreads();

    for (int c = 0; c < NC; c++) {
        int p = c & 1;
        if (c + 1 < NC) ldg_chunk(c + 1);
        compute(p);
        if (c + 1 < NC) sts_chunk(p ^ 1);   // buffer p^1 fully drained last iter
        __syncthreads();
    }

    // ---- epilogue: registers -> global with bias
    #pragma unroll
    for (int mt = 0; mt < 2; mt++) {
        int gr = m0 + wm + mt * 16 + g4;
        #pragma unroll
        for (int nt = 0; nt < NT8; nt++) {
            int gc = n0 + wn + nt * 8 + t4 * 2;
            float2 bv = *(const float2*)(bias + gc);
            if (gr < M) {
                float2 o = make_float2(acc[mt][nt][0] + bv.x, acc[mt][nt][1] + bv.y);
                *(float2*)(C + (size_t)gr * N + gc) = o;
            }
            if (gr + 8 < M) {
                float2 o = make_float2(acc[mt][nt][2] + bv.x, acc[mt][nt][3] + bv.y);
                *(float2*)(C + (size_t)(gr + 8) * N + gc) = o;
            }
        }
    }
}

// ---------------- prep: combined conv kernel --------------------------------
__global__ void prep_kernel(const float* __restrict__ A, const float* __restrict__ Bp,
                            const float* __restrict__ Cp, const float* __restrict__ cw)
{
    __shared__ float U[DU][NSTATE];
    __shared__ float gk[DU];
    __shared__ float sC[NSTATE];
    int tid = threadIdx.x;
    int e = blockIdx.x;
    if (tid < 32) {
        int i = tid & 15;
        float u = 1.f / (1.f + expf(-Bp[i]));
        for (int d = 0; d < DU; d++) {
            if (tid < 16) U[d][i] = u;
            float nu = 0.f;
            #pragma unroll
            for (int j = 0; j < 16; j++)
                nu += A[i*16 + j] * __shfl_sync(0xFFFFFFFFu, u, j);
            u = nu;
        }
    }
    if (tid < 16) sC[tid] = 1.f / (1.f + expf(-Cp[e*16 + tid]));
    __syncthreads();
    for (int d = tid; d < DU; d += blockDim.x) {
        float s = 0.f;
        #pragma unroll
        for (int i = 0; i < 16; i++) s += sC[i] * U[d][i];
        gk[d] = s;
    }
    __syncthreads();
    for (int dd = tid; dd < DK; dd += blockDim.x) {
        float s = 0.f;
        #pragma unroll
        for (int d1 = 0; d1 < 4; d1++) {
            int d2 = dd - d1;
            if (d2 >= 0 && d2 < DU) s += cw[e*4 + (3 - d1)] * gk[d2];
        }
        g_K[e*DK + dd] = s;
    }
}

// ---------------- row L2-normalize ------------------------------------------
__global__ void norm_kernel(float* __restrict__ xp)
{
    int lane = threadIdx.x & 31;
    int row = blockIdx.x * 8 + (threadIdx.x >> 5);
    float* p = xp + (size_t)row * EE;
    float s = 0.f;
    for (int e = lane; e < EE; e += 32) { float v = p[e]; s += v*v; }
    #pragma unroll
    for (int o = 16; o > 0; o >>= 1) s += __shfl_xor_sync(0xFFFFFFFFu, s, o);
    float inv = 1.f / fmaxf(sqrtf(s), 1e-12f);
    for (int e = lane; e < EE; e += 32) p[e] *= inv;
}

// ---------------- attention -------------------------------------------------
__global__ void attn_kernel(const float* __restrict__ qkv,
                            float* __restrict__ att, float* __restrict__ imp)
{
    __shared__ float sq[4][E3];
    __shared__ float sc[4][36];
    __shared__ int   gb[4][NH];
    int wid = threadIdx.x >> 5, lane = threadIdx.x & 31;
    int n = blockIdx.x * 4 + wid;
    const float* row = qkv + (size_t)n * E3;
    float* s = sq[wid];
    for (int e = lane; e < E3; e += 32) s[e] = row[e];
    __syncwarp();
    for (int p = lane; p < 36; p += 32) {
        int h = p / 6, g = p - h*6;
        const float* qp = s + h*HDIM;
        const float* kp = s + EE + g*HDIM;
        float d = 0.f;
        #pragma unroll
        for (int t = 0; t < HDIM; t++) d += qp[t] * kp[t];
        sc[wid][p] = d;
    }
    __syncwarp();
    if (lane < NH) {
        float best = sc[wid][lane*6]; int bg = 0;
        #pragma unroll
        for (int g = 1; g < 6; g++) {
            float v = sc[wid][lane*6 + g];
            if (v > best) { best = v; bg = g; }   // strict > : jax tie -> lowest idx
        }
        gb[wid][lane] = bg;
    }
    __syncwarp();
    float acc = 0.f;
    for (int e = lane; e < EE; e += 32) {
        int h = e % NH, d = e / NH;
        float v = s[2*EE + gb[wid][h]*HDIM + d];
        att[(size_t)n*EE + e] = v;
        acc += v*v;
    }
    #pragma unroll
    for (int o = 16; o > 0; o >>= 1) acc += __shfl_xor_sync(0xFFFFFFFFu, acc, o);
    if (lane == 0) imp[n] = sqrtf(acc);
}

// ---------------- top-819 per batch -----------------------------------------
__global__ void topk_kernel(const float* __restrict__ imp, int* __restrict__ idxout)
{
    __shared__ unsigned long long key[LL];
    int b = blockIdx.x;
    for (int i = threadIdx.x; i < LL; i += blockDim.x) {
        unsigned fb = __float_as_uint(imp[b*LL + i]);
        key[i] = ((unsigned long long)(0xFFFFFFFFu - fb) << 32) | (unsigned)i;
    }
    __syncthreads();
    for (int k = 2; k <= LL; k <<= 1)
        for (int j = k >> 1; j > 0; j >>= 1) {
            for (int i = threadIdx.x; i < LL; i += blockDim.x) {
                int ixj = i ^ j;
                if (ixj > i) {
                    bool up = ((i & k) == 0);
                    unsigned long long a = key[i], c = key[ixj];
                    if ((a > c) == up) { key[i] = c; key[ixj] = a; }
                }
            }
            __syncthreads();
        }
    for (int i = threadIdx.x; i < KC; i += blockDim.x)
        idxout[b*KC + i] = (int)(key[i] & 0xFFFFFFFFu);
}

// ---------------- fused gather + 67-tap causal conv -------------------------
__global__ void __launch_bounds__(224) conv_kernel(const float* __restrict__ att,
                                                   const int* __restrict__ idx,
                                                   float* __restrict__ ys)
{
    const int ET = 56, JT = 64, WIN = JT + DK - 1;
    __shared__ float sp[ET][WIN + 1];
    __shared__ float Ks[ET][DK + 1];
    __shared__ int   sidx[WIN];
    int et = blockIdx.x, jt = blockIdx.y, b = blockIdx.z;
    int e0 = et * ET, j0 = jt * JT;
    int tid = threadIdx.x;

    for (int w = tid; w < WIN; w += 224) {
        int j = j0 - (DK - 1) + w;
        sidx[w] = (j >= 0 && j < KC) ? idx[b*KC + j] : -1;
    }
    for (int i = tid; i < ET*DK; i += 224) {
        int ee = i / DK, d = i - ee*DK;
        Ks[ee][d] = g_K[(e0 + ee)*DK + d];
    }
    __syncthreads();
    for (int i = tid; i < WIN*ET; i += 224) {
        int w = i / ET, ee = i - w*ET;
        int pos = sidx[w];
        sp[ee][w] = (pos >= 0) ? att[((size_t)b*LL + pos)*EE + e0 + ee] : 0.f;
    }
    __syncthreads();

    int ee = tid % ET, jg = tid / ET;
    float acc[16];
    #pragma unroll
    for (int t = 0; t < 16; t++) acc[t] = 0.f;
    int wbase = (DK - 1) + jg*16;
    for (int d = 0; d < DK; d++) {
        float kv = Ks[ee][d];
        #pragma unroll
        for (int t = 0; t < 16; t++)
            acc[t] += kv * sp[ee][wbase + t - d];
    }
    #pragma unroll
    for (int t = 0; t < 16; t++) {
        int j = j0 + jg*16 + t;
        if (j < KC) ys[((size_t)b*KC + j)*EE + e0 + ee] = acc[t];
    }
}

// ---------------- residual copy + scatter -----------------------------------
__global__ void residual_kernel(const float4* __restrict__ x, float4* __restrict__ out)
{
    size_t i = (size_t)blockIdx.x * blockDim.x + threadIdx.x;
    out[i] = x[i];
}

__global__ void scatter_kernel(const float* __restrict__ x, const float* __restrict__ xproc,
                               const int* __restrict__ idx, float* __restrict__ out)
{
    int row = blockIdx.x;
    int b = row / KC, j = row - b*KC;
    int pos = idx[b*KC + j];
    const float* xp = xproc + (size_t)row * DIMC;
    size_t base = ((size_t)b*LL + pos) * DIMC;
    for (int c = threadIdx.x; c < DIMC; c += blockDim.x)
        out[base + c] = x[base + c] + xp[c];
}

// ---------------- launch ----------------------------------------------------
extern "C" void kernel_launch(void* const* d_in, const int* in_sizes, int n_in,
                              void* d_out, int out_size)
{
    const float* x      = (const float*)d_in[0];
    const float* alpha  = (const float*)d_in[1];
    const float* dyt_w  = (const float*)d_in[2];
    const float* dyt_b  = (const float*)d_in[3];
    const float* W_in   = (const float*)d_in[4];
    const float* b_in   = (const float*)d_in[5];
    const float* W_qkv  = (const float*)d_in[6];
    const float* b_qkv  = (const float*)d_in[7];
    const float* conv_w = (const float*)d_in[8];
    const float* A      = (const float*)d_in[9];
    const float* Bp     = (const float*)d_in[10];
    const float* Cp     = (const float*)d_in[11];
    const float* W_out  = (const float*)d_in[12];
    const float* b_out  = (const float*)d_in[13];
    float* out = (float*)d_out;

    float *xp, *qkv, *att, *imp, *ys, *xproc;
    int *idx;
    cudaGetSymbolAddress((void**)&xp,    g_xp);
    cudaGetSymbolAddress((void**)&qkv,   g_qkv);
    cudaGetSymbolAddress((void**)&att,   g_att);
    cudaGetSymbolAddress((void**)&imp,   g_imp);
    cudaGetSymbolAddress((void**)&idx,   g_idx);
    cudaGetSymbolAddress((void**)&ys,    g_ys);
    cudaGetSymbolAddress((void**)&xproc, g_xproc);

    const int SMA = (2*128*36 + 2*32*(112 + 8)) * 4;   // 67584 B (BN=112)
    const int SMB = (2*128*36 + 2*32*(128 + 8)) * 4;   // 71680 B (BN=128)
    cudaFuncSetAttribute(mma_gemm<112,1>, cudaFuncAttributeMaxDynamicSharedMemorySize, SMA);
    cudaFuncSetAttribute(mma_gemm<112,0>, cudaFuncAttributeMaxDynamicSharedMemorySize, SMA);
    cudaFuncSetAttribute(mma_gemm<128,0>, cudaFuncAttributeMaxDynamicSharedMemorySize, SMB);

    // 0) scan->conv kernel precompute
    prep_kernel<<<EE, 128>>>(A, Bp, Cp, conv_w);

    // 1) xp = dyt(x) @ W_in + b_in   [32768,512]x[512,336]
    mma_gemm<112,1><<<dim3(3, NN/128), 256, SMA>>>(x, W_in, b_in, xp,
                                                   NN, EE, DIMC, alpha, dyt_w, dyt_b);

    // 2) row-normalize
    norm_kernel<<<NN/8, 256>>>(xp);

    // 3) qkv = xpn @ W_qkv + b_qkv  [32768,336]x[336,1008]
    mma_gemm<112,0><<<dim3(9, NN/128), 256, SMA>>>(xp, W_qkv, b_qkv, qkv,
                                                   NN, E3, EE, alpha, dyt_w, dyt_b);

    // 4) sparse attention (kh=1 -> argmax gather) + importance
    attn_kernel<<<NN/4, 128>>>(qkv, att, imp);

    // 5) exact sorted top-819 per batch
    topk_kernel<<<BB, 1024>>>(imp, idx);

    // 6) gather + combined dconv*scan causal convolution
    conv_kernel<<<dim3(EE/56, (KC + 63)/64, BB), 224>>>(att, idx, ys);

    // 7) xproc = ys @ W_out + b_out  [6552,336]x[336,512]
    mma_gemm<128,0><<<dim3(4, (BB*KC + 127)/128), 256, SMB>>>(ys, W_out, b_out, xproc,
                                                              BB*KC, DIMC, EE,
                                                              alpha, dyt_w, dyt_b);

    // 8) out = residual
    residual_kernel<<<(NN*DIMC/4)/1024, 1024>>>((const float4*)x, (float4*)out);

    // 9) scatter selected rows
    scatter_kernel<<<BB*KC, 128>>>(x, xproc, idx, out);
}